// round 1
// baseline (speedup 1.0000x reference)
#include <cuda_runtime.h>

#define HT 160
#define WDx 160
#define HWPIX 25600
#define NB 2
#define NPIX (NB * HWPIX)
#define CCH 64
#define NSETC 32

// ---------------- scratch (device globals: no allocation allowed) ----------
__device__ float g_x[NPIX * CCH];     // LN1 output, [b][c][hw]
__device__ float g_att[NPIX * NSETC]; // attention maps [b][n][hw]
__device__ float g_u1[NPIX * CCH];    // conv1x1a output
__device__ float g_uf[NPIX * CCH];    // unfolded-feature conv output
__device__ float g_z[NPIX * CCH];     // pre-conv3 combined
__device__ float g_y[NPIX * CCH];     // mid residual
__device__ float g_xmean[NB * CCH];
__device__ float g_sca[NB * CCH];

// ---------------- K1: LayerNorm over channels (per pixel) ------------------
__global__ void ln1_kernel(const float* __restrict__ inp,
                           const float* __restrict__ w,
                           const float* __restrict__ b) {
    int p = blockIdx.x * blockDim.x + threadIdx.x;
    if (p >= NPIX) return;
    int bi = p / HWPIX, hw = p - bi * HWPIX;
    const float* src = inp + (size_t)bi * CCH * HWPIX + hw;
    float v[64];
    float s = 0.f;
#pragma unroll
    for (int c = 0; c < 64; c++) { v[c] = src[c * HWPIX]; s += v[c]; }
    float mu = s * (1.f / 64.f);
    float q = 0.f;
#pragma unroll
    for (int c = 0; c < 64; c++) { float d = v[c] - mu; q += d * d; }
    float rinv = rsqrtf(q * (1.f / 64.f) + 1e-6f);
    float* dst = g_x + (size_t)bi * CCH * HWPIX + hw;
#pragma unroll
    for (int c = 0; c < 64; c++)
        dst[c * HWPIX] = (v[c] - mu) * rinv * w[c] + b[c];
}

// ---------------- K2: per-(b,c) spatial mean of g_x ------------------------
__global__ void mean_kernel() {
    int bc = blockIdx.x; // 0..127
    const float* src = g_x + (size_t)bc * HWPIX;
    float s = 0.f;
    for (int i = threadIdx.x; i < HWPIX; i += blockDim.x) s += src[i];
#pragma unroll
    for (int o = 16; o > 0; o >>= 1) s += __shfl_down_sync(0xffffffffu, s, o);
    __shared__ float red[8];
    if ((threadIdx.x & 31) == 0) red[threadIdx.x >> 5] = s;
    __syncthreads();
    if (threadIdx.x == 0) {
        float t = 0.f;
        for (int i = 0; i < 8; i++) t += red[i];
        g_xmean[bc] = t * (1.f / HWPIX);
    }
}

// ---------------- K3: sca = 1x1 conv on pooled means -----------------------
__global__ void sca_kernel(const float* __restrict__ w, const float* __restrict__ b) {
    int t = threadIdx.x;
    if (t < NB * CCH) {
        int bi = t >> 6, c = t & 63;
        float a = b[c];
#pragma unroll
        for (int k = 0; k < 64; k++) a += w[c * 64 + k] * g_xmean[bi * 64 + k];
        g_sca[t] = a;
    }
}

// ---------------- K4: attention path (grouped3x3 + gate + 1x1) -------------
__global__ void att_kernel(const float* __restrict__ c2a_w, const float* __restrict__ c2a_b,
                           const float* __restrict__ c2b_w, const float* __restrict__ c2b_b,
                           const float* __restrict__ attgamma) {
    __shared__ float wa[32 * 18];  // c2a weights, same layout as source
    __shared__ float ba[32];
    __shared__ float wbT[16 * 32]; // [j][n]
    __shared__ float bb[32], ag[32];
    for (int i = threadIdx.x; i < 576; i += blockDim.x) wa[i] = c2a_w[i];
    if (threadIdx.x < 32) {
        ba[threadIdx.x] = c2a_b[threadIdx.x];
        bb[threadIdx.x] = c2b_b[threadIdx.x];
        ag[threadIdx.x] = attgamma[threadIdx.x];
    }
    for (int i = threadIdx.x; i < 512; i += blockDim.x) {
        int j = i >> 5, n = i & 31;
        wbT[i] = c2b_w[n * 16 + j];
    }
    __syncthreads();
    int p = blockIdx.x * blockDim.x + threadIdx.x;
    if (p >= NPIX) return;
    int bi = p / HWPIX, hw = p - bi * HWPIX;
    int h = hw / WDx, w = hw - h * WDx;
    const float* xb = g_x + (size_t)bi * CCH * HWPIX;
    float att_acc[32];
#pragma unroll
    for (int n = 0; n < 32; n++) att_acc[n] = 0.f;
#pragma unroll 4
    for (int j = 0; j < 16; j++) {
        float t0 = ba[j], t1 = ba[j + 16];
#pragma unroll
        for (int l = 0; l < 2; l++) {
            const float* xp0 = xb + (2 * j + l) * HWPIX;
            const float* xp1 = xb + (2 * (j + 16) + l) * HWPIX;
#pragma unroll
            for (int dy = 0; dy < 3; dy++) {
                int hy = h + dy - 1;
                bool vy = ((unsigned)hy < HT);
#pragma unroll
                for (int dx = 0; dx < 3; dx++) {
                    int wx = w + dx - 1;
                    bool ok = vy && ((unsigned)wx < WDx);
                    int off = hy * WDx + wx;
                    float x0 = ok ? xp0[off] : 0.f;
                    float x1 = ok ? xp1[off] : 0.f;
                    t0 += wa[j * 18 + l * 9 + dy * 3 + dx] * x0;
                    t1 += wa[(j + 16) * 18 + l * 9 + dy * 3 + dx] * x1;
                }
            }
        }
        float gj = t0 * t1;
        const float4* wp = (const float4*)&wbT[j * 32];
#pragma unroll
        for (int n4 = 0; n4 < 8; n4++) {
            float4 wv = wp[n4];
            att_acc[4 * n4 + 0] += wv.x * gj;
            att_acc[4 * n4 + 1] += wv.y * gj;
            att_acc[4 * n4 + 2] += wv.z * gj;
            att_acc[4 * n4 + 3] += wv.w * gj;
        }
    }
    float* dst = g_att + (size_t)bi * NSETC * HWPIX + hw;
#pragma unroll
    for (int n = 0; n < 32; n++)
        dst[n * HWPIX] = (att_acc[n] + bb[n]) * ag[n];
}

// ---------------- K5: 1x1 conv 64->64 (c11a) on g_x -> g_u1 ----------------
__global__ void conv1x1_u1(const float* __restrict__ w, const float* __restrict__ b) {
    __shared__ float ws[4096];
    __shared__ float bs[64];
    for (int i = threadIdx.x; i < 4096; i += blockDim.x) ws[i] = w[i];
    if (threadIdx.x < 64) bs[threadIdx.x] = b[threadIdx.x];
    __syncthreads();
    int p = blockIdx.x * blockDim.x + threadIdx.x;
    if (p >= NPIX) return;
    int bi = p / HWPIX, hw = p - bi * HWPIX;
    const float* src = g_x + (size_t)bi * CCH * HWPIX + hw;
    float xin[64];
#pragma unroll
    for (int i = 0; i < 64; i++) xin[i] = src[i * HWPIX];
    float* dst = g_u1 + (size_t)bi * CCH * HWPIX + hw;
#pragma unroll 4
    for (int o = 0; o < 64; o++) {
        float a = bs[o];
        const float4* wp = (const float4*)&ws[o * 64];
#pragma unroll
        for (int i4 = 0; i4 < 16; i4++) {
            float4 wv = wp[i4];
            a += wv.x * xin[4 * i4] + wv.y * xin[4 * i4 + 1] +
                 wv.z * xin[4 * i4 + 2] + wv.w * xin[4 * i4 + 3];
        }
        dst[o * HWPIX] = a;
    }
}

// ---------------- K6: grouped 5x5 conv (16 groups of 4) g_u1 -> g_uf -------
__global__ void uf_kernel(const float* __restrict__ w5, const float* __restrict__ b5) {
    __shared__ float ws[6400]; // [g][ic][kk][oc]
    __shared__ float bs[64];
    for (int i = threadIdx.x; i < 6400; i += blockDim.x) {
        int oc = i & 3;
        int r = i >> 2;          // g*100 + ic*25 + kk
        int g = r / 100;
        int r2 = r - g * 100;
        int ic = r2 / 25, kk = r2 - ic * 25;
        // source layout: w5[(g*4+oc)*4 + ic][kk] -> ((g*4+oc)*4+ic)*25 + kk
        ws[i] = w5[((g * 4 + oc) * 4 + ic) * 25 + kk];
    }
    if (threadIdx.x < 64) bs[threadIdx.x] = b5[threadIdx.x];
    __syncthreads();
    int p = blockIdx.x * blockDim.x + threadIdx.x;
    if (p >= NPIX) return;
    int bi = p / HWPIX, hw = p - bi * HWPIX;
    int h = hw / WDx, w = hw - h * WDx;
    const float* ub = g_u1 + (size_t)bi * CCH * HWPIX;
    float* dst = g_uf + (size_t)bi * CCH * HWPIX + hw;
    for (int g = 0; g < 16; g++) {
        float a0 = bs[g * 4 + 0], a1 = bs[g * 4 + 1], a2 = bs[g * 4 + 2], a3 = bs[g * 4 + 3];
        const float* gin = ub + (g * 4) * HWPIX;
#pragma unroll
        for (int dy = 0; dy < 5; dy++) {
            int hy = h + dy - 2;
            bool vy = ((unsigned)hy < HT);
#pragma unroll
            for (int dx = 0; dx < 5; dx++) {
                int wx = w + dx - 2;
                bool ok = vy && ((unsigned)wx < WDx);
                int off = hy * WDx + wx;
                int kk = dy * 5 + dx;
#pragma unroll
                for (int ic = 0; ic < 4; ic++) {
                    float v = ok ? gin[ic * HWPIX + off] : 0.f;
                    const float4 wv = *(const float4*)&ws[(g * 100 + ic * 25 + kk) * 4];
                    a0 += wv.x * v; a1 += wv.y * v; a2 += wv.z * v; a3 += wv.w * v;
                }
            }
        }
        dst[(g * 4 + 0) * HWPIX] = a0;
        dst[(g * 4 + 1) * HWPIX] = a1;
        dst[(g * 4 + 2) * HWPIX] = a2;
        dst[(g * 4 + 3) * HWPIX] = a3;
    }
}

// ---------------- K7: fused KBA + *ga1 + uf + *sca -> g_z ------------------
__global__ void kba_kernel(const float* __restrict__ kb_w,
                           const float* __restrict__ kb_b,
                           const float* __restrict__ ga1) {
    __shared__ float Wg[144 * 32]; // [col][n], col = o*36+i
    __shared__ float kbb[64 * 32]; // [c][n]
    int tid = threadIdx.x;
    for (int idx = tid; idx < 2048; idx += blockDim.x) {
        int c = idx >> 5, n = idx & 31;
        kbb[idx] = kb_b[n * 64 + c];
    }
    int p = blockIdx.x * blockDim.x + tid;
    bool active = (p < NPIX);
    int bi = 0, hw = 0, h = 0, w = 0;
    float att[32];
    if (active) {
        bi = p / HWPIX; hw = p - bi * HWPIX;
        h = hw / WDx; w = hw - h * WDx;
        const float* ap = g_att + (size_t)bi * NSETC * HWPIX + hw;
#pragma unroll
        for (int n = 0; n < 32; n++) att[n] = ap[n * HWPIX];
    }
    for (int g = 0; g < 16; g++) {
        __syncthreads();
        for (int idx = tid; idx < 4608; idx += blockDim.x) {
            int col = idx >> 5, n = idx & 31;
            Wg[idx] = kb_w[n * 2304 + g * 144 + col];
        }
        __syncthreads();
        if (!active) continue;
        // gather 4-channel 3x3 patch of g_uf
        float patch[36];
        const float* ub = g_uf + (size_t)bi * CCH * HWPIX + (g * 4) * HWPIX;
#pragma unroll
        for (int dy = 0; dy < 3; dy++) {
            int hy = h + dy - 1;
            bool vy = ((unsigned)hy < HT);
#pragma unroll
            for (int dx = 0; dx < 3; dx++) {
                int wx = w + dx - 1;
                bool ok = vy && ((unsigned)wx < WDx);
                int off = hy * WDx + wx;
#pragma unroll
                for (int ci = 0; ci < 4; ci++)
                    patch[ci * 9 + dy * 3 + dx] = ok ? ub[ci * HWPIX + off] : 0.f;
            }
        }
#pragma unroll
        for (int o = 0; o < 4; o++) {
            int c = g * 4 + o;
            float acc = 0.f;
            const float4* bp = (const float4*)&kbb[c * 32];
#pragma unroll
            for (int n4 = 0; n4 < 8; n4++) {
                float4 bv = bp[n4];
                acc += att[4 * n4] * bv.x + att[4 * n4 + 1] * bv.y +
                       att[4 * n4 + 2] * bv.z + att[4 * n4 + 3] * bv.w;
            }
#pragma unroll
            for (int i = 0; i < 36; i++) {
                const float4* wp = (const float4*)&Wg[(o * 36 + i) * 32];
                float a = 0.f;
#pragma unroll
                for (int n4 = 0; n4 < 8; n4++) {
                    float4 wv = wp[n4];
                    a += att[4 * n4] * wv.x + att[4 * n4 + 1] * wv.y +
                         att[4 * n4 + 2] * wv.z + att[4 * n4 + 3] * wv.w;
                }
                acc += a * patch[i];
            }
            float ufc = patch[o * 9 + 4]; // center tap = uf value at this channel
            float z = (acc * ga1[c] + ufc) * g_sca[bi * 64 + c];
            g_z[(size_t)bi * CCH * HWPIX + c * HWPIX + hw] = z;
        }
    }
}

// ---------------- K8: conv3 (1x1) + beta residual -> g_y -------------------
__global__ void conv3_res_kernel(const float* __restrict__ inp,
                                 const float* __restrict__ w,
                                 const float* __restrict__ b,
                                 const float* __restrict__ beta) {
    __shared__ float ws[4096];
    __shared__ float bs[64];
    for (int i = threadIdx.x; i < 4096; i += blockDim.x) ws[i] = w[i];
    if (threadIdx.x < 64) bs[threadIdx.x] = b[threadIdx.x];
    __syncthreads();
    int p = blockIdx.x * blockDim.x + threadIdx.x;
    if (p >= NPIX) return;
    int bi = p / HWPIX, hw = p - bi * HWPIX;
    const float* src = g_z + (size_t)bi * CCH * HWPIX + hw;
    const float* rsd = inp + (size_t)bi * CCH * HWPIX + hw;
    float xin[64];
#pragma unroll
    for (int i = 0; i < 64; i++) xin[i] = src[i * HWPIX];
    float* dst = g_y + (size_t)bi * CCH * HWPIX + hw;
#pragma unroll 4
    for (int o = 0; o < 64; o++) {
        float a = bs[o];
        const float4* wp = (const float4*)&ws[o * 64];
#pragma unroll
        for (int i4 = 0; i4 < 16; i4++) {
            float4 wv = wp[i4];
            a += wv.x * xin[4 * i4] + wv.y * xin[4 * i4 + 1] +
                 wv.z * xin[4 * i4 + 2] + wv.w * xin[4 * i4 + 3];
        }
        dst[o * HWPIX] = rsd[o * HWPIX] + a * beta[o];
    }
}

// ---------------- K9: LN2 + FFN (conv4, gate, conv5) + gamma residual ------
__global__ void ffn_kernel(const float* __restrict__ ln2w, const float* __restrict__ ln2b,
                           const float* __restrict__ w4, const float* __restrict__ b4,
                           const float* __restrict__ w5, const float* __restrict__ b5,
                           const float* __restrict__ gamma, float* __restrict__ out) {
    __shared__ float ws[12288]; // [0:8192) w4 [j][i], [8192:12288) w5T [j][o]
    for (int i = threadIdx.x; i < 8192; i += blockDim.x) ws[i] = w4[i];
    for (int i = threadIdx.x; i < 4096; i += blockDim.x) {
        int j = i >> 6, o = i & 63;
        ws[8192 + i] = w5[o * 64 + j];
    }
    __syncthreads();
    int p = blockIdx.x * blockDim.x + threadIdx.x;
    if (p >= NPIX) return;
    int bi = p / HWPIX, hw = p - bi * HWPIX;
    const float* yb = g_y + (size_t)bi * CCH * HWPIX + hw;
    float v[64];
    float s = 0.f;
#pragma unroll
    for (int c = 0; c < 64; c++) { v[c] = yb[c * HWPIX]; s += v[c]; }
    float mu = s * (1.f / 64.f);
    float q = 0.f;
#pragma unroll
    for (int c = 0; c < 64; c++) { float d = v[c] - mu; q += d * d; }
    float rinv = rsqrtf(q * (1.f / 64.f) + 1e-6f);
    float xn[64];
#pragma unroll
    for (int c = 0; c < 64; c++) xn[c] = (v[c] - mu) * rinv * ln2w[c] + ln2b[c];
    float acc[64];
#pragma unroll
    for (int o = 0; o < 64; o++) acc[o] = 0.f;
    for (int j = 0; j < 64; j++) {
        float a = b4[j], bb = b4[j + 64];
        const float4* wpa = (const float4*)&ws[j * 64];
        const float4* wpb = (const float4*)&ws[(j + 64) * 64];
#pragma unroll
        for (int i4 = 0; i4 < 16; i4++) {
            float4 wva = wpa[i4];
            float4 wvb = wpb[i4];
            a  += wva.x * xn[4 * i4] + wva.y * xn[4 * i4 + 1] + wva.z * xn[4 * i4 + 2] + wva.w * xn[4 * i4 + 3];
            bb += wvb.x * xn[4 * i4] + wvb.y * xn[4 * i4 + 1] + wvb.z * xn[4 * i4 + 2] + wvb.w * xn[4 * i4 + 3];
        }
        float gj = a * bb;
        const float4* wp5 = (const float4*)&ws[8192 + j * 64];
#pragma unroll
        for (int o4 = 0; o4 < 16; o4++) {
            float4 wv = wp5[o4];
            acc[4 * o4 + 0] += wv.x * gj;
            acc[4 * o4 + 1] += wv.y * gj;
            acc[4 * o4 + 2] += wv.z * gj;
            acc[4 * o4 + 3] += wv.w * gj;
        }
    }
    float* dst = out + (size_t)bi * CCH * HWPIX + hw;
#pragma unroll
    for (int o = 0; o < 64; o++)
        dst[o * HWPIX] = v[o] + (acc[o] + b5[o]) * gamma[o];
}

// ---------------------------------------------------------------------------
extern "C" void kernel_launch(void* const* d_in, const int* in_sizes, int n_in,
                              void* d_out, int out_size) {
    const float* inp      = (const float*)d_in[0];
    const float* ln1_w    = (const float*)d_in[1];
    const float* ln1_b    = (const float*)d_in[2];
    const float* ln2_w    = (const float*)d_in[3];
    const float* ln2_b    = (const float*)d_in[4];
    const float* sca_w    = (const float*)d_in[5];
    const float* sca_b    = (const float*)d_in[6];
    const float* c11a_w   = (const float*)d_in[7];
    const float* c11a_b   = (const float*)d_in[8];
    const float* c11b_w   = (const float*)d_in[9];
    const float* c11b_b   = (const float*)d_in[10];
    const float* c2a_w    = (const float*)d_in[11];
    const float* c2a_b    = (const float*)d_in[12];
    const float* c2b_w    = (const float*)d_in[13];
    const float* c2b_b    = (const float*)d_in[14];
    const float* conv3_w  = (const float*)d_in[15];
    const float* conv3_b  = (const float*)d_in[16];
    const float* conv4_w  = (const float*)d_in[17];
    const float* conv4_b  = (const float*)d_in[18];
    const float* conv5_w  = (const float*)d_in[19];
    const float* conv5_b  = (const float*)d_in[20];
    const float* kb_w     = (const float*)d_in[21];
    const float* kb_b     = (const float*)d_in[22];
    const float* ga1      = (const float*)d_in[23];
    const float* attgamma = (const float*)d_in[24];
    const float* beta     = (const float*)d_in[25];
    const float* gamma    = (const float*)d_in[26];
    float* out = (float*)d_out;

    ln1_kernel<<<NPIX / 256, 256>>>(inp, ln1_w, ln1_b);
    mean_kernel<<<NB * CCH, 256>>>();
    sca_kernel<<<1, 128>>>(sca_w, sca_b);
    att_kernel<<<NPIX / 256, 256>>>(c2a_w, c2a_b, c2b_w, c2b_b, attgamma);
    conv1x1_u1<<<NPIX / 256, 256>>>(c11a_w, c11a_b);
    uf_kernel<<<NPIX / 256, 256>>>(c11b_w, c11b_b);
    kba_kernel<<<NPIX / 128, 128>>>(kb_w, kb_b, ga1);
    conv3_res_kernel<<<NPIX / 256, 256>>>(inp, conv3_w, conv3_b, beta);
    ffn_kernel<<<NPIX / 128, 128>>>(ln2_w, ln2_b, conv4_w, conv4_b,
                                    conv5_w, conv5_b, gamma, out);
}